// round 5
// baseline (speedup 1.0000x reference)
#include <cuda_runtime.h>
#include <cuda_fp8.h>

// COAT Coat_quantize_bgn forward, group_size = 16.
// x: [4, 4096, 4096] f32 (67108864 elems)
// out layout (concat, f32): [x passthrough (n)] [Q (n)] [Oscale (n/16)]
//
// 4 threads per group-of-16; SEG=8 float4 per thread at block-coherent stride.
// All loads front-batched, all stores back-batched: long same-direction DRAM
// bursts to minimize read/write turnaround. No bounds checks (16777216 float4
// divides exactly into 8192 blocks x 2048).

#define COAT_E4M3_MAX 448.0f
#define SEG 8
#define TPB 256

__global__ void __launch_bounds__(TPB)
coat_quantize_kernel(const float4* __restrict__ x4,
                     float4* __restrict__ out_x4,
                     float4* __restrict__ out_q4,
                     float* __restrict__ out_s)
{
    int tid = threadIdx.x;
    int base = blockIdx.x * (TPB * SEG) + tid;

    // ---- read phase: 8 independent LDG.128 in flight ----
    float4 v[SEG];
#pragma unroll
    for (int k = 0; k < SEG; k++)
        v[k] = __ldcs(&x4[base + k * TPB]);

    // ---- compute: group amax (4 lanes/group) -> scale -> fp8 grid ----
    float scale[SEG];
    float4 q[SEG];
#pragma unroll
    for (int k = 0; k < SEG; k++) {
        float a = fmaxf(fmaxf(fabsf(v[k].x), fabsf(v[k].y)),
                        fmaxf(fabsf(v[k].z), fabsf(v[k].w)));
        a = fmaxf(a, __shfl_xor_sync(0xffffffffu, a, 1));
        a = fmaxf(a, __shfl_xor_sync(0xffffffffu, a, 2));
        float s = (a == 0.0f) ? 1.0f : __fdiv_rn(a, COAT_E4M3_MAX);
        scale[k] = s;
        q[k].x = float(__nv_fp8_e4m3(__fdiv_rn(v[k].x, s)));
        q[k].y = float(__nv_fp8_e4m3(__fdiv_rn(v[k].y, s)));
        q[k].z = float(__nv_fp8_e4m3(__fdiv_rn(v[k].z, s)));
        q[k].w = float(__nv_fp8_e4m3(__fdiv_rn(v[k].w, s)));
    }

    // ---- write phase: long same-direction store bursts ----
#pragma unroll
    for (int k = 0; k < SEG; k++)
        __stcs(&out_x4[base + k * TPB], v[k]);
#pragma unroll
    for (int k = 0; k < SEG; k++)
        __stcs(&out_q4[base + k * TPB], q[k]);
    if ((tid & 3) == 0) {
#pragma unroll
        for (int k = 0; k < SEG; k++)
            __stcs(&out_s[(base + k * TPB) >> 2], scale[k]);
    }
}

extern "C" void kernel_launch(void* const* d_in, const int* in_sizes, int n_in,
                              void* d_out, int out_size)
{
    const float* x = (const float*)d_in[0];
    int n = in_sizes[0];              // 67108864
    int n4 = n >> 2;                  // 16777216 float4

    float* out = (float*)d_out;
    float4* out_x4 = (float4*)out;               // [n]   passthrough
    float4* out_q4 = (float4*)(out + (size_t)n); // [n]   Q
    float*  out_s  = out + 2 * (size_t)n;        // [n/16] Oscale

    int per_block = TPB * SEG;                   // 2048
    int blocks = n4 / per_block;                 // 8192 (exact)
    coat_quantize_kernel<<<blocks, TPB>>>(
        (const float4*)x, out_x4, out_q4, out_s);
}

// round 6
// speedup vs baseline: 1.1051x; 1.1051x over previous
#include <cuda_runtime.h>
#include <cuda_fp8.h>

// COAT Coat_quantize_bgn forward, group_size = 16.
// x: [4, 4096, 4096] f32 (67108864 elems)
// out layout (concat, f32): [x passthrough (n)] [Q (n)] [Oscale (n/16)]
//
// 4 threads per group-of-16; SEG=4 float4 per thread at block-coherent stride
// (every LDG/STG.128 fully coalesced, MLP=4). Streaming hints (.cs): zero reuse.
// No bounds checks: 16777216 float4 = 16384 blocks x 1024 exactly.

#define COAT_E4M3_MAX 448.0f
#define SEG 4
#define TPB 256

__global__ void __launch_bounds__(TPB)
coat_quantize_kernel(const float4* __restrict__ x4,
                     float4* __restrict__ out_x4,
                     float4* __restrict__ out_q4,
                     float* __restrict__ out_s)
{
    int tid = threadIdx.x;
    int base = blockIdx.x * (TPB * SEG) + tid;

    // Front-batched loads: 4 independent LDG.128 in flight per thread.
    float4 v[SEG];
#pragma unroll
    for (int k = 0; k < SEG; k++)
        v[k] = __ldcs(&x4[base + k * TPB]);

    // Group amax (4 consecutive lanes = one group of 16) -> scale.
    float scale[SEG];
#pragma unroll
    for (int k = 0; k < SEG; k++) {
        float a = fmaxf(fmaxf(fabsf(v[k].x), fabsf(v[k].y)),
                        fmaxf(fabsf(v[k].z), fabsf(v[k].w)));
        a = fmaxf(a, __shfl_xor_sync(0xffffffffu, a, 1));
        a = fmaxf(a, __shfl_xor_sync(0xffffffffu, a, 2));
        scale[k] = (a == 0.0f) ? 1.0f : __fdiv_rn(a, COAT_E4M3_MAX);
    }

    // Quantize to e4m3 grid (RN, satfinite — matches XLA) and store.
#pragma unroll
    for (int k = 0; k < SEG; k++) {
        int i = base + k * TPB;
        float s = scale[k];
        float4 q;
        q.x = float(__nv_fp8_e4m3(__fdiv_rn(v[k].x, s)));
        q.y = float(__nv_fp8_e4m3(__fdiv_rn(v[k].y, s)));
        q.z = float(__nv_fp8_e4m3(__fdiv_rn(v[k].z, s)));
        q.w = float(__nv_fp8_e4m3(__fdiv_rn(v[k].w, s)));

        __stcs(&out_x4[i], v[k]);   // passthrough
        __stcs(&out_q4[i], q);      // quantized (fp8 grid, f32 view)
        if ((tid & 3) == 0)
            __stcs(&out_s[i >> 2], s);
    }
}

extern "C" void kernel_launch(void* const* d_in, const int* in_sizes, int n_in,
                              void* d_out, int out_size)
{
    const float* x = (const float*)d_in[0];
    int n = in_sizes[0];              // 67108864
    int n4 = n >> 2;                  // 16777216 float4

    float* out = (float*)d_out;
    float4* out_x4 = (float4*)out;               // [n]   passthrough
    float4* out_q4 = (float4*)(out + (size_t)n); // [n]   Q
    float*  out_s  = out + 2 * (size_t)n;        // [n/16] Oscale

    int per_block = TPB * SEG;                   // 1024
    int blocks = n4 / per_block;                 // 16384 (exact)
    coat_quantize_kernel<<<blocks, TPB>>>(
        (const float4*)x, out_x4, out_q4, out_s);
}

// round 7
// speedup vs baseline: 1.1060x; 1.0008x over previous
#include <cuda_runtime.h>
#include <cuda_fp8.h>

// COAT Coat_quantize_bgn forward, group_size = 16.
// x: [4, 4096, 4096] f32 (67108864 elems)
// out layout (concat, f32): [x passthrough (n)] [Q (n)] [Oscale (n/16)]
//
// 4 threads per group-of-16; SEG=2 float4 per thread, TPB=512: highest
// simultaneous (occupancy x MLP) point on the measured frontier.
// All LDG/STG.128 fully coalesced; streaming hints (.cs): zero reuse.
// No bounds checks: 16777216 float4 = 16384 blocks x 1024 exactly.

#define COAT_E4M3_MAX 448.0f
#define SEG 2
#define TPB 512

__global__ void __launch_bounds__(TPB)
coat_quantize_kernel(const float4* __restrict__ x4,
                     float4* __restrict__ out_x4,
                     float4* __restrict__ out_q4,
                     float* __restrict__ out_s)
{
    int tid = threadIdx.x;
    int base = blockIdx.x * (TPB * SEG) + tid;

    // Front-batched loads: 2 independent LDG.128 in flight per thread.
    float4 v[SEG];
#pragma unroll
    for (int k = 0; k < SEG; k++)
        v[k] = __ldcs(&x4[base + k * TPB]);

    // Group amax (4 consecutive lanes = one group of 16) -> scale.
    float scale[SEG];
#pragma unroll
    for (int k = 0; k < SEG; k++) {
        float a = fmaxf(fmaxf(fabsf(v[k].x), fabsf(v[k].y)),
                        fmaxf(fabsf(v[k].z), fabsf(v[k].w)));
        a = fmaxf(a, __shfl_xor_sync(0xffffffffu, a, 1));
        a = fmaxf(a, __shfl_xor_sync(0xffffffffu, a, 2));
        scale[k] = (a == 0.0f) ? 1.0f : __fdiv_rn(a, COAT_E4M3_MAX);
    }

    // Quantize to e4m3 grid (RN, satfinite — matches XLA) and store.
#pragma unroll
    for (int k = 0; k < SEG; k++) {
        int i = base + k * TPB;
        float s = scale[k];
        float4 q;
        q.x = float(__nv_fp8_e4m3(__fdiv_rn(v[k].x, s)));
        q.y = float(__nv_fp8_e4m3(__fdiv_rn(v[k].y, s)));
        q.z = float(__nv_fp8_e4m3(__fdiv_rn(v[k].z, s)));
        q.w = float(__nv_fp8_e4m3(__fdiv_rn(v[k].w, s)));

        __stcs(&out_x4[i], v[k]);   // passthrough
        __stcs(&out_q4[i], q);      // quantized (fp8 grid, f32 view)
        if ((tid & 3) == 0)
            __stcs(&out_s[i >> 2], s);
    }
}

extern "C" void kernel_launch(void* const* d_in, const int* in_sizes, int n_in,
                              void* d_out, int out_size)
{
    const float* x = (const float*)d_in[0];
    int n = in_sizes[0];              // 67108864
    int n4 = n >> 2;                  // 16777216 float4

    float* out = (float*)d_out;
    float4* out_x4 = (float4*)out;               // [n]   passthrough
    float4* out_q4 = (float4*)(out + (size_t)n); // [n]   Q
    float*  out_s  = out + 2 * (size_t)n;        // [n/16] Oscale

    int per_block = TPB * SEG;                   // 1024
    int blocks = n4 / per_block;                 // 16384 (exact)
    coat_quantize_kernel<<<blocks, TPB>>>(
        (const float4*)x, out_x4, out_q4, out_s);
}